// round 15
// baseline (speedup 1.0000x reference)
#include <cuda_runtime.h>
#include <cuda_fp16.h>
#include <cstdint>

// VectorQuantizer: z [32,256,64,64] f32, emb [1024,256] f32
// out = concat( z_q [32,256,64,64] f32 , idx [131072] f32 )
//
// R15: mma path reverted byte-identical to R11 (545us, proven). New split:
//   scan_kernel: pure-streaming top-2 over g_dist rows -> g_b12/g_idx
//   repair:      fast-exit on sound margin EPS, else exhaustive exact
//                (R4-verified bit-exact arithmetic).
// Loop-carried top-2 inside the mma loop is POISON (R12-14: 17ms) - avoided.

#define N_TOK   131072
#define KDIM    256
#define NEMB    1024
#define CH_STRIDE 4096
#define B_STRIDE  (256*4096)
#define EPS 3e-3f

__device__ float  g_esq[NEMB];
__device__ __half g_Bh[NEMB * KDIM];                 // 512 KB fp16 emb
__device__ float  g_dist[(size_t)N_TOK * NEMB];      // 512 MB approx distances
__device__ int    g_idx[N_TOK];
__device__ float2 g_b12[N_TOK];

// ---- SMEM layout (dynamic) ----
#define SA_H 0          // A hi: 256 k-rows x 128 tok fp16 (swizzled)  64KB
#define SB   65536      // B double buffer: 2 x 16KB                   32KB
#define SESQ 98304      // esq 4KB
#define SM_TOTAL 102400

__device__ __forceinline__ uint32_t smem_u32(const void* p) {
    uint32_t a;
    asm("{ .reg .u64 t; cvta.to.shared.u64 t, %1; cvt.u32.u64 %0, t; }" : "=r"(a) : "l"(p));
    return a;
}
__device__ __forceinline__ void ldsm4(uint32_t* r, uint32_t a) {
    asm volatile("ldmatrix.sync.aligned.m8n8.x4.shared.b16 {%0,%1,%2,%3}, [%4];"
                 : "=r"(r[0]), "=r"(r[1]), "=r"(r[2]), "=r"(r[3]) : "r"(a));
}
__device__ __forceinline__ void ldsm4t(uint32_t* r, uint32_t a) {
    asm volatile("ldmatrix.sync.aligned.m8n8.x4.trans.shared.b16 {%0,%1,%2,%3}, [%4];"
                 : "=r"(r[0]), "=r"(r[1]), "=r"(r[2]), "=r"(r[3]) : "r"(a));
}
__device__ __forceinline__ void mma16816(float* c, const uint32_t* a, const uint32_t* b) {
    asm volatile("mma.sync.aligned.m16n8k16.row.col.f32.f16.f16.f32 "
                 "{%0,%1,%2,%3}, {%4,%5,%6,%7}, {%8,%9}, {%0,%1,%2,%3};"
                 : "+f"(c[0]), "+f"(c[1]), "+f"(c[2]), "+f"(c[3])
                 : "r"(a[0]), "r"(a[1]), "r"(a[2]), "r"(a[3]), "r"(b[0]), "r"(b[1]));
}
#define CP_COMMIT() asm volatile("cp.async.commit_group;" ::: "memory")
#define CP_WAIT1()  asm volatile("cp.async.wait_group 1;" ::: "memory")
#define CP_WAIT0()  asm volatile("cp.async.wait_group 0;" ::: "memory")

// ======================= Kernel: esq (exact, XLA order) ====================
__global__ void esq_kernel(const float* __restrict__ emb) {
    int warp = (blockIdx.x * blockDim.x + threadIdx.x) >> 5;
    int lane = threadIdx.x & 31;
    if (warp >= NEMB) return;
    const float* row = emb + (size_t)warp * KDIM;
    float s = 0.f;
#pragma unroll
    for (int c = lane; c < KDIM; c += 32) {
        float v = row[c];
        s = __fadd_rn(s, __fmul_rn(v, v));
    }
#pragma unroll
    for (int o = 16; o; o >>= 1)
        s = __fadd_rn(s, __shfl_xor_sync(0xffffffffu, s, o));
    if (lane == 0) g_esq[warp] = s;
}

// ======================= Kernel: convert emb -> fp16 =======================
__global__ void convB_kernel(const float* __restrict__ emb) {
    int i = (blockIdx.x * 256 + threadIdx.x) * 4;
    float4 v = *(const float4*)(emb + i);
    __half2 a = __floats2half2_rn(v.x, v.y);
    __half2 b = __floats2half2_rn(v.z, v.w);
    *(uint2*)(g_Bh + i) = make_uint2(*(uint32_t*)&a, *(uint32_t*)&b);
}

// ======================= Kernel: mma.sync GEMM + d-store (R11 exact) =======
__device__ __forceinline__ void issueB(uint32_t smem_base, int cc, int tid) {
#pragma unroll
    for (int j = 0; j < 4; j++) {
        int idx = tid + j * 256;          // 0..1023 16B granules
        int n = idx >> 5;                 // row within chunk 0..31
        int c = idx & 31;                 // 16B col within row
        const char* src = (const char*)g_Bh + (size_t)(cc * 32 + n) * 512 + (size_t)c * 16;
        uint32_t dst = smem_base + SB + (uint32_t)((cc & 1) * 16384
                     + n * 512 + ((c ^ (n & 7)) << 4));
        asm volatile("cp.async.cg.shared.global [%0], [%1], 16;" :: "r"(dst), "l"(src) : "memory");
    }
    CP_COMMIT();
}

__global__ __launch_bounds__(256, 2)
void mma_kernel(const float* __restrict__ z) {
    extern __shared__ char smem[];
    const uint32_t smem_base = smem_u32(smem);
    const int tid  = threadIdx.x;
    const int lane = tid & 31;
    const int wid  = tid >> 5;
    const int n0   = blockIdx.x * 128;
    const int b    = n0 >> 12;
    const int hw0  = n0 & 4095;
    const float* zbase = z + (size_t)b * B_STRIDE + hw0;

    float* esq_s = (float*)(smem + SESQ);

    // prefetch first two B chunks
    issueB(smem_base, 0, tid);
    issueB(smem_base, 1, tid);

    for (int i = tid; i < NEMB; i += 256) esq_s[i] = g_esq[i];

    // ---- convert A: z fp32 -> fp16 hi, k-major swizzled smem ----
#pragma unroll
    for (int it = 0; it < 16; it++) {
        int g  = tid + it * 256;          // granule 0..4095
        int c  = g >> 4;                  // channel (k)
        int gt = g & 15;                  // token granule (8 tokens)
        const float* src = zbase + (size_t)c * CH_STRIDE + gt * 8;
        float4 v0 = *(const float4*)(src);
        float4 v1 = *(const float4*)(src + 4);
        __half2 h0 = __floats2half2_rn(v0.x, v0.y);
        __half2 h1 = __floats2half2_rn(v0.z, v0.w);
        __half2 h2 = __floats2half2_rn(v1.x, v1.y);
        __half2 h3 = __floats2half2_rn(v1.z, v1.w);
        uint32_t ph[4] = {*(uint32_t*)&h0, *(uint32_t*)&h1, *(uint32_t*)&h2, *(uint32_t*)&h3};
        uint32_t off = (uint32_t)c * 256 + (uint32_t)((gt ^ (c & 7)) << 4);
        *(uint4*)(smem + SA_H + off) = *(uint4*)ph;
    }

    // ---- per-lane ldmatrix address bases ----
    const int l7  = lane & 7;
    const int lt1 = (lane >> 3) & 1;
    const int lt2 = (lane >> 4) & 1;
    const int M0  = wid * 16;
    const uint32_t aoff = (uint32_t)(lt2 * 8 + l7) * 256
                        + (uint32_t)((((M0 >> 3) + lt1) ^ l7) << 4);
    const uint32_t addrAh = smem_base + SA_H + aoff;

    const int gID = lane >> 2;
    const int tIG = lane & 3;

    __syncthreads();   // A + esq ready

    // ---- load ALL A fragments into registers (chunk-invariant) ----
    uint32_t Ah[16][4];
#pragma unroll
    for (int kk = 0; kk < 16; kk++)
        ldsm4t(Ah[kk], addrAh + (uint32_t)kk * 4096);

    // d-store row bases: this thread owns token rows (M0+gID) and (M0+gID+8)
    float* drow0 = g_dist + (size_t)(n0 + M0 + gID) * NEMB;
    float* drow1 = drow0 + (size_t)8 * NEMB;

    for (int ec = 0; ec < 32; ec++) {
        if (ec < 31) { CP_WAIT1(); } else { CP_WAIT0(); }
        __syncthreads();
        const uint32_t bufb = smem_base + SB + (uint32_t)((ec & 1) * 16384);
        const uint32_t brow0 = bufb + (uint32_t)((lt2 * 8 + l7) * 512);        // codes 0..15
        const uint32_t brow1 = bufb + (uint32_t)(((16 + lt2 * 8 + l7)) * 512); // codes 16..31

        float acc[4][4];
#pragma unroll
        for (int t = 0; t < 4; t++)
#pragma unroll
            for (int r = 0; r < 4; r++) acc[t][r] = 0.f;

#pragma unroll
        for (int kk = 0; kk < 16; kk++) {
            const uint32_t kchunk = (uint32_t)(kk * 2) + (uint32_t)lt1;
            const uint32_t sw = ((kchunk ^ (uint32_t)l7) << 4);
            uint32_t bh0[4], bh1[4];
            ldsm4(bh0, brow0 + sw);
            ldsm4(bh1, brow1 + sw);
            mma16816(acc[0], Ah[kk], &bh0[0]);
            mma16816(acc[1], Ah[kk], &bh0[2]);
            mma16816(acc[2], Ah[kk], &bh1[0]);
            mma16816(acc[3], Ah[kk], &bh1[2]);
        }

        // ---- d = esq - 2*dot, store row-major (cols e0, e0+1) ----
#pragma unroll
        for (int t = 0; t < 4; t++) {
            int e0 = ec * 32 + t * 8 + tIG * 2;   // 0..1022, float2-aligned
            float2 e2 = *(const float2*)&esq_s[e0];
            float2 d0, d1;
            d0.x = __fmaf_rn(-2.0f, acc[t][0], e2.x);
            d0.y = __fmaf_rn(-2.0f, acc[t][1], e2.y);
            d1.x = __fmaf_rn(-2.0f, acc[t][2], e2.x);
            d1.y = __fmaf_rn(-2.0f, acc[t][3], e2.y);
            *(float2*)(drow0 + e0) = d0;
            *(float2*)(drow1 + e0) = d1;
        }
        __syncthreads();
        if (ec < 30) issueB(smem_base, ec + 2, tid);
    }
}

// ======================= Kernel: scan (warp/token top-2 stream) ============
__global__ __launch_bounds__(256)
void scan_kernel() {
    const int wl   = threadIdx.x >> 5;
    const int lane = threadIdx.x & 31;
    const int n = blockIdx.x * 8 + wl;
    const float* drow = g_dist + (size_t)n * NEMB;

    float b1 = 3.0e38f, b2 = 3.0e38f;
    int   bi = 0;
#pragma unroll 8
    for (int i = 0; i < 32; i++) {
        float d = drow[lane + 32 * i];
        bool p = d < b1;
        b2 = p ? b1 : fminf(b2, d);
        bi = p ? (lane + 32 * i) : bi;
        b1 = fminf(b1, d);
    }
#pragma unroll
    for (int o = 16; o; o >>= 1) {
        float ob1 = __shfl_xor_sync(0xffffffffu, b1, o);
        float ob2 = __shfl_xor_sync(0xffffffffu, b2, o);
        int   obi = __shfl_xor_sync(0xffffffffu, bi, o);
        bool p = ob1 < b1;
        b2 = fminf(p ? fminf(b1, ob2) : b2, p ? 3.0e38f : ob1);
        bi = p ? obi : bi;
        b1 = fminf(b1, ob1);
    }
    if (lane == 0) {
        g_idx[n] = bi;
        g_b12[n] = make_float2(b1, b2);
    }
}

// ======================= Kernel: repair (margin gate + exhaustive) =========
__global__ __launch_bounds__(256)
void repair_kernel(const float* __restrict__ z, const float* __restrict__ emb) {
    const int lane = threadIdx.x & 31;
    const int n = blockIdx.x * 8 + (threadIdx.x >> 5);
    float2 bb = g_b12[n];
    if (bb.y > bb.x + EPS) return;     // approx argmin provably == reference

    const int b = n >> 12, hw = n & 4095;
    const float* zb = z + (size_t)b * B_STRIDE + hw;

    // z_sq: XLA row-reduce order (lane-strided c = lane+32i, unfused, xor tree)
    float s = 0.f;
#pragma unroll
    for (int i = 0; i < 8; i++) {
        float v = zb[(size_t)(lane + 32 * i) * CH_STRIDE];
        s = __fadd_rn(s, __fmul_rn(v, v));
    }
#pragma unroll
    for (int o = 16; o; o >>= 1)
        s = __fadd_rn(s, __shfl_xor_sync(0xffffffffu, s, o));
    float zsq = s;

    // exact chains, lane-strided over all codes
    float m = 3.0e38f; int mi = 0x7fffffff;
#pragma unroll 1
    for (int base = 0; base < NEMB; base += 32) {
        int e = base + lane;
        const float* er = emb + (size_t)e * KDIM;
        float acc = 0.f;
#pragma unroll 8
        for (int c = 0; c < KDIM; c++)
            acc = __fmaf_rn(zb[(size_t)c * CH_STRIDE], er[c], acc);
        float A = __fadd_rn(zsq, g_esq[e]);
        float d = __fsub_rn(A, __fmul_rn(2.0f, acc));
        if (d < m || (d == m && e < mi)) { m = d; mi = e; }
    }
#pragma unroll
    for (int o = 16; o; o >>= 1) {
        float om = __shfl_xor_sync(0xffffffffu, m, o);
        int   oi = __shfl_xor_sync(0xffffffffu, mi, o);
        if (om < m || (om == m && oi < mi)) { m = om; mi = oi; }
    }
    if (lane == 0) g_idx[n] = mi;
}

// ======================= Kernel: gather/scatter ============================
__global__ __launch_bounds__(256)
void scatter_kernel(const float* __restrict__ emb, float* __restrict__ out,
                    float* __restrict__ out_idx, int write_idx) {
    const int tid = threadIdx.x;
    const int n0 = blockIdx.x * 128;
    const int b = n0 >> 12, hw0 = n0 & 4095;
    float* obase = out + (size_t)b * B_STRIDE + hw0;
    const int tok = tid & 127;
    const int half = tid >> 7;
    const int myidx = g_idx[n0 + tok];
    if (tid < 128 && write_idx) out_idx[n0 + tid] = (float)g_idx[n0 + tid];
    const float* erow = emb + (size_t)myidx * KDIM;
#pragma unroll 4
    for (int c = half; c < KDIM; c += 2)
        obase[(size_t)c * CH_STRIDE + tok] = erow[c];
}

// ---------------------------------------------------------------------------
extern "C" void kernel_launch(void* const* d_in, const int* in_sizes, int n_in,
                              void* d_out, int out_size) {
    const float* z   = (const float*)d_in[0];
    const float* emb = (const float*)d_in[1];
    float* out = (float*)d_out;

    const int zq_elems = 32 * 256 * 64 * 64;
    int write_idx = (out_size >= zq_elems + N_TOK) ? 1 : 0;

    cudaFuncSetAttribute(mma_kernel, cudaFuncAttributeMaxDynamicSharedMemorySize, SM_TOTAL);

    esq_kernel<<<128, 256>>>(emb);
    convB_kernel<<<256, 256>>>(emb);
    mma_kernel<<<N_TOK / 128, 256, SM_TOTAL>>>(z);
    scan_kernel<<<N_TOK / 8, 256>>>();
    repair_kernel<<<N_TOK / 8, 256>>>(z, emb);
    scatter_kernel<<<N_TOK / 128, 256>>>(emb, out, out + zq_elems, write_idx);
}

// round 16
// speedup vs baseline: 32.0704x; 32.0704x over previous
#include <cuda_runtime.h>
#include <cuda_fp16.h>
#include <cstdint>

// VectorQuantizer: z [32,256,64,64] f32, emb [1024,256] f32
// out = concat( z_q [32,256,64,64] f32 , idx [131072] f32 )
//
// R16 = R11 (545us champion, proven) with ONE change: g_dist stored as fp16
// (halves the 512MB distance store in mma and the re-read in repair).
// Same 5 kernels, same launch list, NO g_b12 / margin-gate (R12-15's 17ms
// correlates with exactly that plumbing). Repair keeps R11's structure:
// row scan -> candidate gather -> exact chains (R4-verified bit-exact).

#define N_TOK   131072
#define KDIM    256
#define NEMB    1024
#define CH_STRIDE 4096
#define B_STRIDE  (256*4096)
#define EPS 3e-3f

__device__ float  g_esq[NEMB];
__device__ __half g_Bh[NEMB * KDIM];                 // 512 KB fp16 emb
__device__ __half g_dist[(size_t)N_TOK * NEMB];      // 256 MB approx distances
__device__ int    g_idx[N_TOK];

// ---- SMEM layout (dynamic) ----
#define SA_H 0          // A hi: 256 k-rows x 128 tok fp16 (swizzled)  64KB
#define SB   65536      // B double buffer: 2 x 16KB                   32KB
#define SESQ 98304      // esq 4KB
#define SM_TOTAL 102400

__device__ __forceinline__ uint32_t smem_u32(const void* p) {
    uint32_t a;
    asm("{ .reg .u64 t; cvta.to.shared.u64 t, %1; cvt.u32.u64 %0, t; }" : "=r"(a) : "l"(p));
    return a;
}
__device__ __forceinline__ void ldsm4(uint32_t* r, uint32_t a) {
    asm volatile("ldmatrix.sync.aligned.m8n8.x4.shared.b16 {%0,%1,%2,%3}, [%4];"
                 : "=r"(r[0]), "=r"(r[1]), "=r"(r[2]), "=r"(r[3]) : "r"(a));
}
__device__ __forceinline__ void ldsm4t(uint32_t* r, uint32_t a) {
    asm volatile("ldmatrix.sync.aligned.m8n8.x4.trans.shared.b16 {%0,%1,%2,%3}, [%4];"
                 : "=r"(r[0]), "=r"(r[1]), "=r"(r[2]), "=r"(r[3]) : "r"(a));
}
__device__ __forceinline__ void mma16816(float* c, const uint32_t* a, const uint32_t* b) {
    asm volatile("mma.sync.aligned.m16n8k16.row.col.f32.f16.f16.f32 "
                 "{%0,%1,%2,%3}, {%4,%5,%6,%7}, {%8,%9}, {%0,%1,%2,%3};"
                 : "+f"(c[0]), "+f"(c[1]), "+f"(c[2]), "+f"(c[3])
                 : "r"(a[0]), "r"(a[1]), "r"(a[2]), "r"(a[3]), "r"(b[0]), "r"(b[1]));
}
#define CP_COMMIT() asm volatile("cp.async.commit_group;" ::: "memory")
#define CP_WAIT1()  asm volatile("cp.async.wait_group 1;" ::: "memory")
#define CP_WAIT0()  asm volatile("cp.async.wait_group 0;" ::: "memory")

// ======================= Kernel: esq (exact, XLA order) ====================
__global__ void esq_kernel(const float* __restrict__ emb) {
    int warp = (blockIdx.x * blockDim.x + threadIdx.x) >> 5;
    int lane = threadIdx.x & 31;
    if (warp >= NEMB) return;
    const float* row = emb + (size_t)warp * KDIM;
    float s = 0.f;
#pragma unroll
    for (int c = lane; c < KDIM; c += 32) {
        float v = row[c];
        s = __fadd_rn(s, __fmul_rn(v, v));
    }
#pragma unroll
    for (int o = 16; o; o >>= 1)
        s = __fadd_rn(s, __shfl_xor_sync(0xffffffffu, s, o));
    if (lane == 0) g_esq[warp] = s;
}

// ======================= Kernel: convert emb -> fp16 =======================
__global__ void convB_kernel(const float* __restrict__ emb) {
    int i = (blockIdx.x * 256 + threadIdx.x) * 4;
    float4 v = *(const float4*)(emb + i);
    __half2 a = __floats2half2_rn(v.x, v.y);
    __half2 b = __floats2half2_rn(v.z, v.w);
    *(uint2*)(g_Bh + i) = make_uint2(*(uint32_t*)&a, *(uint32_t*)&b);
}

// ======================= Kernel: mma.sync GEMM + d-store ===================
__device__ __forceinline__ void issueB(uint32_t smem_base, int cc, int tid) {
#pragma unroll
    for (int j = 0; j < 4; j++) {
        int idx = tid + j * 256;          // 0..1023 16B granules
        int n = idx >> 5;                 // row within chunk 0..31
        int c = idx & 31;                 // 16B col within row
        const char* src = (const char*)g_Bh + (size_t)(cc * 32 + n) * 512 + (size_t)c * 16;
        uint32_t dst = smem_base + SB + (uint32_t)((cc & 1) * 16384
                     + n * 512 + ((c ^ (n & 7)) << 4));
        asm volatile("cp.async.cg.shared.global [%0], [%1], 16;" :: "r"(dst), "l"(src) : "memory");
    }
    CP_COMMIT();
}

__global__ __launch_bounds__(256, 2)
void mma_kernel(const float* __restrict__ z) {
    extern __shared__ char smem[];
    const uint32_t smem_base = smem_u32(smem);
    const int tid  = threadIdx.x;
    const int lane = tid & 31;
    const int wid  = tid >> 5;
    const int n0   = blockIdx.x * 128;
    const int b    = n0 >> 12;
    const int hw0  = n0 & 4095;
    const float* zbase = z + (size_t)b * B_STRIDE + hw0;

    float* esq_s = (float*)(smem + SESQ);

    // prefetch first two B chunks
    issueB(smem_base, 0, tid);
    issueB(smem_base, 1, tid);

    for (int i = tid; i < NEMB; i += 256) esq_s[i] = g_esq[i];

    // ---- convert A: z fp32 -> fp16 hi, k-major swizzled smem ----
#pragma unroll
    for (int it = 0; it < 16; it++) {
        int g  = tid + it * 256;          // granule 0..4095
        int c  = g >> 4;                  // channel (k)
        int gt = g & 15;                  // token granule (8 tokens)
        const float* src = zbase + (size_t)c * CH_STRIDE + gt * 8;
        float4 v0 = *(const float4*)(src);
        float4 v1 = *(const float4*)(src + 4);
        __half2 h0 = __floats2half2_rn(v0.x, v0.y);
        __half2 h1 = __floats2half2_rn(v0.z, v0.w);
        __half2 h2 = __floats2half2_rn(v1.x, v1.y);
        __half2 h3 = __floats2half2_rn(v1.z, v1.w);
        uint32_t ph[4] = {*(uint32_t*)&h0, *(uint32_t*)&h1, *(uint32_t*)&h2, *(uint32_t*)&h3};
        uint32_t off = (uint32_t)c * 256 + (uint32_t)((gt ^ (c & 7)) << 4);
        *(uint4*)(smem + SA_H + off) = *(uint4*)ph;
    }

    // ---- per-lane ldmatrix address bases ----
    const int l7  = lane & 7;
    const int lt1 = (lane >> 3) & 1;
    const int lt2 = (lane >> 4) & 1;
    const int M0  = wid * 16;
    const uint32_t aoff = (uint32_t)(lt2 * 8 + l7) * 256
                        + (uint32_t)((((M0 >> 3) + lt1) ^ l7) << 4);
    const uint32_t addrAh = smem_base + SA_H + aoff;

    const int gID = lane >> 2;
    const int tIG = lane & 3;

    __syncthreads();   // A + esq ready

    // ---- load ALL A fragments into registers (chunk-invariant) ----
    uint32_t Ah[16][4];
#pragma unroll
    for (int kk = 0; kk < 16; kk++)
        ldsm4t(Ah[kk], addrAh + (uint32_t)kk * 4096);

    // d-store row bases: this thread owns token rows (M0+gID) and (M0+gID+8)
    __half* drow0 = g_dist + (size_t)(n0 + M0 + gID) * NEMB;
    __half* drow1 = drow0 + (size_t)8 * NEMB;

    for (int ec = 0; ec < 32; ec++) {
        if (ec < 31) { CP_WAIT1(); } else { CP_WAIT0(); }
        __syncthreads();
        const uint32_t bufb = smem_base + SB + (uint32_t)((ec & 1) * 16384);
        const uint32_t brow0 = bufb + (uint32_t)((lt2 * 8 + l7) * 512);        // codes 0..15
        const uint32_t brow1 = bufb + (uint32_t)(((16 + lt2 * 8 + l7)) * 512); // codes 16..31

        float acc[4][4];
#pragma unroll
        for (int t = 0; t < 4; t++)
#pragma unroll
            for (int r = 0; r < 4; r++) acc[t][r] = 0.f;

#pragma unroll
        for (int kk = 0; kk < 16; kk++) {
            const uint32_t kchunk = (uint32_t)(kk * 2) + (uint32_t)lt1;
            const uint32_t sw = ((kchunk ^ (uint32_t)l7) << 4);
            uint32_t bh0[4], bh1[4];
            ldsm4(bh0, brow0 + sw);
            ldsm4(bh1, brow1 + sw);
            mma16816(acc[0], Ah[kk], &bh0[0]);
            mma16816(acc[1], Ah[kk], &bh0[2]);
            mma16816(acc[2], Ah[kk], &bh1[0]);
            mma16816(acc[3], Ah[kk], &bh1[2]);
        }

        // ---- d = esq - 2*dot, store row-major as fp16 (cols e0, e0+1) ----
#pragma unroll
        for (int t = 0; t < 4; t++) {
            int e0 = ec * 32 + t * 8 + tIG * 2;   // 0..1022, half2-aligned
            float2 e2 = *(const float2*)&esq_s[e0];
            __half2 h0 = __floats2half2_rn(__fmaf_rn(-2.0f, acc[t][0], e2.x),
                                           __fmaf_rn(-2.0f, acc[t][1], e2.y));
            __half2 h1 = __floats2half2_rn(__fmaf_rn(-2.0f, acc[t][2], e2.x),
                                           __fmaf_rn(-2.0f, acc[t][3], e2.y));
            *(__half2*)(drow0 + e0) = h0;
            *(__half2*)(drow1 + e0) = h1;
        }
        __syncthreads();
        if (ec < 30) issueB(smem_base, ec + 2, tid);
    }
}

// ======================= Kernel: repair (warp per token) ===================
// R11 structure: scan row top-2; margin holds -> done; else gather candidates
// and run exact chains (bit-exact R4-verified arithmetic).
__global__ __launch_bounds__(256)
void repair_kernel(const float* __restrict__ z, const float* __restrict__ emb) {
    __shared__ short cands[8][64];
    __shared__ int   ccnt[8];
    const int wl   = threadIdx.x >> 5;
    const int lane = threadIdx.x & 31;
    const int n = blockIdx.x * 8 + wl;
    const __half2* drow2 = (const __half2*)(g_dist + (size_t)n * NEMB);

    // top-2 scan of d row (128B per iteration, 16 iters)
    float b1 = 3.0e38f, b2 = 3.0e38f;
    int   bi = 0;
#pragma unroll 4
    for (int i = 0; i < 16; i++) {
        float2 dv = __half22float2(drow2[lane + 32 * i]);
        int e = 2 * (lane + 32 * i);
        if (dv.x < b1) { b2 = b1; b1 = dv.x; bi = e; }
        else if (dv.x < b2) b2 = dv.x;
        if (dv.y < b1) { b2 = b1; b1 = dv.y; bi = e + 1; }
        else if (dv.y < b2) b2 = dv.y;
    }
#pragma unroll
    for (int o = 16; o; o >>= 1) {
        float ob1 = __shfl_xor_sync(0xffffffffu, b1, o);
        float ob2 = __shfl_xor_sync(0xffffffffu, b2, o);
        int   obi = __shfl_xor_sync(0xffffffffu, bi, o);
        if (ob1 < b1 || (ob1 == b1 && obi < bi)) {
            b2 = fminf(b1, ob2); b1 = ob1; bi = obi;
        } else {
            b2 = fminf(b2, ob1);
        }
    }
    if (b2 > b1 + EPS) {
        if (lane == 0) g_idx[n] = bi;
        return;
    }

    // ---- ambiguous: gather candidates within EPS of b1 ----
    if (lane == 0) ccnt[wl] = 0;
    __syncwarp();
#pragma unroll 4
    for (int i = 0; i < 16; i++) {
        float2 dv = __half22float2(drow2[lane + 32 * i]);
        int e = 2 * (lane + 32 * i);
        if (dv.x <= b1 + EPS) {
            int p = atomicAdd(&ccnt[wl], 1);
            if (p < 64) cands[wl][p] = (short)e;
        }
        if (dv.y <= b1 + EPS) {
            int p = atomicAdd(&ccnt[wl], 1);
            if (p < 64) cands[wl][p] = (short)(e + 1);
        }
    }
    __syncwarp();
    int total = ccnt[wl];
    int full = (total > 64);
    int ncand = full ? NEMB : total;

    const int b = n >> 12, hw = n & 4095;
    const float* zb = z + (size_t)b * B_STRIDE + hw;

    // z_sq: XLA row-reduce order (lane-strided c = lane+32i, unfused, xor tree)
    float s = 0.f;
#pragma unroll
    for (int i = 0; i < 8; i++) {
        float v = zb[(size_t)(lane + 32 * i) * CH_STRIDE];
        s = __fadd_rn(s, __fmul_rn(v, v));
    }
#pragma unroll
    for (int o = 16; o; o >>= 1)
        s = __fadd_rn(s, __shfl_xor_sync(0xffffffffu, s, o));
    float zsq = s;

    // exact chains, lane-strided over candidates
    float m = 3.0e38f; int mi = 0x7fffffff;
    for (int base = 0; base < ncand; base += 32) {
        int j = base + lane;
        if (j < ncand) {
            int e = full ? j : (int)cands[wl][j];
            const float* er = emb + (size_t)e * KDIM;
            float acc = 0.f;
#pragma unroll 8
            for (int c = 0; c < KDIM; c++)
                acc = __fmaf_rn(zb[(size_t)c * CH_STRIDE], er[c], acc);
            float A = __fadd_rn(zsq, g_esq[e]);
            float d = __fsub_rn(A, __fmul_rn(2.0f, acc));
            if (d < m || (d == m && e < mi)) { m = d; mi = e; }
        }
    }
#pragma unroll
    for (int o = 16; o; o >>= 1) {
        float om = __shfl_xor_sync(0xffffffffu, m, o);
        int   oi = __shfl_xor_sync(0xffffffffu, mi, o);
        if (om < m || (om == m && oi < mi)) { m = om; mi = oi; }
    }
    if (lane == 0) g_idx[n] = mi;
}

// ======================= Kernel: gather/scatter ============================
__global__ __launch_bounds__(256)
void scatter_kernel(const float* __restrict__ emb, float* __restrict__ out,
                    float* __restrict__ out_idx, int write_idx) {
    const int tid = threadIdx.x;
    const int n0 = blockIdx.x * 128;
    const int b = n0 >> 12, hw0 = n0 & 4095;
    float* obase = out + (size_t)b * B_STRIDE + hw0;
    const int tok = tid & 127;
    const int half = tid >> 7;
    const int myidx = g_idx[n0 + tok];
    if (tid < 128 && write_idx) out_idx[n0 + tid] = (float)g_idx[n0 + tid];
    const float* erow = emb + (size_t)myidx * KDIM;
#pragma unroll 4
    for (int c = half; c < KDIM; c += 2)
        obase[(size_t)c * CH_STRIDE + tok] = erow[c];
}

// ---------------------------------------------------------------------------
extern "C" void kernel_launch(void* const* d_in, const int* in_sizes, int n_in,
                              void* d_out, int out_size) {
    const float* z   = (const float*)d_in[0];
    const float* emb = (const float*)d_in[1];
    float* out = (float*)d_out;

    const int zq_elems = 32 * 256 * 64 * 64;
    int write_idx = (out_size >= zq_elems + N_TOK) ? 1 : 0;

    cudaFuncSetAttribute(mma_kernel, cudaFuncAttributeMaxDynamicSharedMemorySize, SM_TOTAL);

    esq_kernel<<<128, 256>>>(emb);
    convB_kernel<<<256, 256>>>(emb);
    mma_kernel<<<N_TOK / 128, 256, SM_TOTAL>>>(z);
    repair_kernel<<<N_TOK / 8, 256>>>(z, emb);
    scatter_kernel<<<N_TOK / 128, 256>>>(emb, out, out + zq_elems, write_idx);
}